// round 14
// baseline (speedup 1.0000x reference)
#include <cuda_runtime.h>
#include <cuda_fp16.h>
#include <cstdint>

#define NMAX   100000
#define HWORDS 50000          // packed uint16x2 degree words
#define RHALF  50000          // nodes per dst-range (2 ranges)
#define SL     74             // slices per range: 2*74 = 148 agg blocks
#define DB     148            // deg blocks

// Scratch (device globals; no allocation allowed)
__device__ float    g_dinv[NMAX];
__device__ __align__(16) __half   g_ph[NMAX];        // p = dinv*x (200KB, L1-res)
__device__ __align__(16) __half   g_rh[NMAX];        // rho = dinv*(g0-g1) (200KB)
__device__ float    g_rhof[NMAX];                    // rho fp32 for self-loop
__device__ __align__(16) uint32_t g_dpart[DB * HWORDS];  // deg per-block partials
__device__ __align__(16) float    g_part1[SL * NMAX];    // agg1 slice partials
__device__ __align__(16) float    g_part2[SL * NMAX];    // agg2 slice partials

// -------- degree: smem hist, STG-partial flush (no REDG) --------

__global__ void k_deg(const int* __restrict__ dst, int E) {
    extern __shared__ uint32_t hist[];  // HWORDS words = 200KB
    for (int i = threadIdx.x; i < HWORDS; i += blockDim.x) hist[i] = 0u;
    __syncthreads();

    int e8 = E >> 3;
    int stride = gridDim.x * blockDim.x;
    for (int i = blockIdx.x * blockDim.x + threadIdx.x; i < e8; i += stride) {
        int4 a = __ldcg(reinterpret_cast<const int4*>(dst) + 2 * i);
        int4 b = __ldcg(reinterpret_cast<const int4*>(dst) + 2 * i + 1);
        atomicAdd(&hist[a.x >> 1], 1u << ((a.x & 1) * 16));
        atomicAdd(&hist[a.y >> 1], 1u << ((a.y & 1) * 16));
        atomicAdd(&hist[a.z >> 1], 1u << ((a.z & 1) * 16));
        atomicAdd(&hist[a.w >> 1], 1u << ((a.w & 1) * 16));
        atomicAdd(&hist[b.x >> 1], 1u << ((b.x & 1) * 16));
        atomicAdd(&hist[b.y >> 1], 1u << ((b.y & 1) * 16));
        atomicAdd(&hist[b.z >> 1], 1u << ((b.z & 1) * 16));
        atomicAdd(&hist[b.w >> 1], 1u << ((b.w & 1) * 16));
    }
    if (blockIdx.x == 0) {  // tail (E % 8)
        for (int e = (e8 << 3) + (int)threadIdx.x; e < E; e += blockDim.x) {
            int d = dst[e];
            atomicAdd(&hist[d >> 1], 1u << ((d & 1) * 16));
        }
    }
    __syncthreads();

    for (int i = threadIdx.x; i < HWORDS; i += blockDim.x)
        g_dpart[blockIdx.x * HWORDS + i] = hist[i];  // coalesced STG
}

// ---- node1: sum deg partials (2 nodes/thread), dinv, half p ----

__global__ void k_node1(const float* __restrict__ x) {
    int stride = gridDim.x * blockDim.x;
    for (int i = blockIdx.x * blockDim.x + threadIdx.x; i < HWORDS; i += stride) {
        unsigned sum = 0;  // u16x2 lanes never overflow (deg <= ~110)
        #pragma unroll 4
        for (int b = 0; b < DB; b++) sum += g_dpart[b * HWORDS + i];
        int n0 = 2 * i, n1 = 2 * i + 1;
        float d0 = rsqrtf(1.0f + (float)(sum & 0xFFFFu));   // +1 = self-loop
        float d1 = rsqrtf(1.0f + (float)(sum >> 16));
        g_dinv[n0] = d0;
        g_dinv[n1] = d1;
        g_ph[n0] = __float2half(d0 * x[n0]);
        g_ph[n1] = __float2half(d1 * x[n1]);
    }
}

// ---- generic agg pass: 2 dst-ranges x 74 slices, smem tile, half gathers ----

__device__ __forceinline__ void agg_pass(const int* __restrict__ src,
                                         const int* __restrict__ dst, int E,
                                         const __half* __restrict__ vals,
                                         float* __restrict__ part,
                                         float* tile) {
    int range = blockIdx.x / SL;
    int slice = blockIdx.x % SL;
    int lo = range * RHALF;
    for (int i = threadIdx.x; i < RHALF; i += blockDim.x) tile[i] = 0.0f;
    __syncthreads();

    int e8 = E >> 3;
    for (int i = slice * (int)blockDim.x + (int)threadIdx.x; i < e8;
         i += SL * (int)blockDim.x) {
        int4 sa = __ldcg(reinterpret_cast<const int4*>(src) + 2 * i);
        int4 sb = __ldcg(reinterpret_cast<const int4*>(src) + 2 * i + 1);
        int4 da = __ldcg(reinterpret_cast<const int4*>(dst) + 2 * i);
        int4 db = __ldcg(reinterpret_cast<const int4*>(dst) + 2 * i + 1);
        int t0 = da.x - lo, t1 = da.y - lo, t2 = da.z - lo, t3 = da.w - lo;
        int t4 = db.x - lo, t5 = db.y - lo, t6 = db.z - lo, t7 = db.w - lo;
        // predicated gathers (no branch around the LDG)
        float v0 = ((unsigned)t0 < RHALF) ? __half2float(__ldg(&vals[sa.x])) : 0.0f;
        float v1 = ((unsigned)t1 < RHALF) ? __half2float(__ldg(&vals[sa.y])) : 0.0f;
        float v2 = ((unsigned)t2 < RHALF) ? __half2float(__ldg(&vals[sa.z])) : 0.0f;
        float v3 = ((unsigned)t3 < RHALF) ? __half2float(__ldg(&vals[sa.w])) : 0.0f;
        float v4 = ((unsigned)t4 < RHALF) ? __half2float(__ldg(&vals[sb.x])) : 0.0f;
        float v5 = ((unsigned)t5 < RHALF) ? __half2float(__ldg(&vals[sb.y])) : 0.0f;
        float v6 = ((unsigned)t6 < RHALF) ? __half2float(__ldg(&vals[sb.z])) : 0.0f;
        float v7 = ((unsigned)t7 < RHALF) ? __half2float(__ldg(&vals[sb.w])) : 0.0f;
        if ((unsigned)t0 < RHALF) atomicAdd(&tile[t0], v0);
        if ((unsigned)t1 < RHALF) atomicAdd(&tile[t1], v1);
        if ((unsigned)t2 < RHALF) atomicAdd(&tile[t2], v2);
        if ((unsigned)t3 < RHALF) atomicAdd(&tile[t3], v3);
        if ((unsigned)t4 < RHALF) atomicAdd(&tile[t4], v4);
        if ((unsigned)t5 < RHALF) atomicAdd(&tile[t5], v5);
        if ((unsigned)t6 < RHALF) atomicAdd(&tile[t6], v6);
        if ((unsigned)t7 < RHALF) atomicAdd(&tile[t7], v7);
    }
    if (slice == 0) {  // tail (E % 8), predicated by range
        for (int e = (e8 << 3) + (int)threadIdx.x; e < E; e += blockDim.x) {
            int t = dst[e] - lo;
            if ((unsigned)t < RHALF)
                atomicAdd(&tile[t], __half2float(__ldg(&vals[src[e]])));
        }
    }
    __syncthreads();

    for (int i = threadIdx.x; i < RHALF; i += blockDim.x) {
        int v = lo + i;
        if (v < NMAX) part[slice * NMAX + v] = tile[i];  // coalesced STG
    }
}

__global__ void __launch_bounds__(1024, 1)
k_agg1(const int* __restrict__ src, const int* __restrict__ dst, int E) {
    extern __shared__ float tile[];
    agg_pass(src, dst, E, g_ph, g_part1, tile);
}

__global__ void __launch_bounds__(1024, 1)
k_agg2(const int* __restrict__ src, const int* __restrict__ dst, int E) {
    extern __shared__ float tile[];
    agg_pass(src, dst, E, g_rh, g_part2, tile);
}

// ---- node2: sum agg1 partials + self-loop, MLP, emit rho ----

__global__ void k_node2(const float* __restrict__ x,
                        const float* __restrict__ W1, const float* __restrict__ b1,
                        const float* __restrict__ W2, int n) {
    int stride = gridDim.x * blockDim.x;
    for (int i = blockIdx.x * blockDim.x + threadIdx.x; i < n; i += stride) {
        float acc = 0.0f;
        #pragma unroll 2
        for (int s = 0; s < SL; s++) acc += g_part1[s * NMAX + i];
        float dv = g_dinv[i];
        acc += dv * x[i];          // self-loop term (full precision)
        float sv = dv * acc;       // layer-1 aggregated scalar
        float g0 = 0.0f, g1 = 0.0f;
        #pragma unroll
        for (int j = 0; j < 16; j++) {
            float h = fmaxf(fmaf(sv, __ldg(&W1[j]), __ldg(&b1[j])), 0.0f);
            g0 = fmaf(h, __ldg(&W2[2 * j + 0]), g0);
            g1 = fmaf(h, __ldg(&W2[2 * j + 1]), g1);
        }
        float rho = dv * (g0 - g1);   // scalar layer-2 message (z0-z1 channel)
        g_rh[i] = __float2half(rho);
        g_rhof[i] = rho;
    }
}

// ---- output: delta = dv*sum(rho) + (b2_0-b2_1); 2-class log_softmax ----

__global__ void k_out(const float* __restrict__ b2, float* __restrict__ out, int n) {
    float db2 = __ldg(&b2[0]) - __ldg(&b2[1]);
    int stride = gridDim.x * blockDim.x;
    for (int i = blockIdx.x * blockDim.x + threadIdx.x; i < n; i += stride) {
        float acc = g_rhof[i];  // self-loop rho (fp32)
        #pragma unroll 2
        for (int s = 0; s < SL; s++) acc += g_part2[s * NMAX + i];
        float delta = fmaf(g_dinv[i], acc, db2);  // z0 - z1
        float l = log1pf(expf(-fabsf(delta)));
        float o0 = (delta >= 0.0f) ? -l : (delta - l);  // z0 - lse
        float o1 = o0 - delta;                          // z1 - lse
        reinterpret_cast<float2*>(out)[i] = make_float2(o0, o1);
    }
}

// ---------------- launch ----------------

extern "C" void kernel_launch(void* const* d_in, const int* in_sizes, int n_in,
                              void* d_out, int out_size) {
    const float* x  = (const float*)d_in[0];
    const int*   ei = (const int*)  d_in[1];
    const float* W1 = (const float*)d_in[2];
    const float* b1 = (const float*)d_in[3];
    const float* W2 = (const float*)d_in[4];
    const float* b2 = (const float*)d_in[5];
    int n = in_sizes[0];        // 100000
    int E = in_sizes[1] / 2;
    const int* src = ei;
    const int* dst = ei + E;

    const int HIST_BYTES = HWORDS * 4;  // 200 KB
    const int TILE_BYTES = RHALF * 4;   // 200 KB
    cudaFuncSetAttribute(k_deg,  cudaFuncAttributeMaxDynamicSharedMemorySize, HIST_BYTES);
    cudaFuncSetAttribute(k_agg1, cudaFuncAttributeMaxDynamicSharedMemorySize, TILE_BYTES);
    cudaFuncSetAttribute(k_agg2, cudaFuncAttributeMaxDynamicSharedMemorySize, TILE_BYTES);

    k_deg  <<<DB, 1024, HIST_BYTES>>>(dst, E);
    k_node1<<<148, 512>>>(x);
    k_agg1 <<<2 * SL, 1024, TILE_BYTES>>>(src, dst, E);
    k_node2<<<148, 512>>>(x, W1, b1, W2, n);
    k_agg2 <<<2 * SL, 1024, TILE_BYTES>>>(src, dst, E);
    k_out  <<<148, 512>>>(b2, (float*)d_out, n);
}

// round 15
// speedup vs baseline: 1.3065x; 1.3065x over previous
#include <cuda_runtime.h>
#include <cuda_fp16.h>
#include <cstdint>

#define NMAX   100000
#define HWORDS 50000          // packed uint16x2 degree words
#define RHALF  50000          // nodes per dst-range (2 ranges)
#define SL     74             // slices per range: 2*74 = 148 agg blocks
#define DB     148            // deg blocks

// Scratch (device globals; no allocation allowed)
__device__ float    g_dinv[NMAX];
__device__ __align__(16) __half   g_ph[NMAX];        // p = dinv*x (200KB, L1-res)
__device__ __align__(16) __half   g_rh[NMAX];        // rho = dinv*(g0-g1) (200KB)
__device__ float    g_rhof[NMAX];                    // rho fp32 for self-loop
__device__ __align__(16) uint32_t g_dpart[DB * HWORDS];  // deg per-block partials
__device__ __align__(16) float    g_part1[SL * NMAX];    // agg1 slice partials
__device__ __align__(16) float    g_part2[SL * NMAX];    // agg2 slice partials

// -------- degree: smem hist, STG-partial flush (no REDG) --------

__global__ void k_deg(const int* __restrict__ dst, int E) {
    extern __shared__ uint32_t hist[];  // HWORDS words = 200KB
    for (int i = threadIdx.x; i < HWORDS; i += blockDim.x) hist[i] = 0u;
    __syncthreads();

    int e8 = E >> 3;
    int stride = gridDim.x * blockDim.x;
    for (int i = blockIdx.x * blockDim.x + threadIdx.x; i < e8; i += stride) {
        int4 a = __ldcg(reinterpret_cast<const int4*>(dst) + 2 * i);
        int4 b = __ldcg(reinterpret_cast<const int4*>(dst) + 2 * i + 1);
        atomicAdd(&hist[a.x >> 1], 1u << ((a.x & 1) * 16));
        atomicAdd(&hist[a.y >> 1], 1u << ((a.y & 1) * 16));
        atomicAdd(&hist[a.z >> 1], 1u << ((a.z & 1) * 16));
        atomicAdd(&hist[a.w >> 1], 1u << ((a.w & 1) * 16));
        atomicAdd(&hist[b.x >> 1], 1u << ((b.x & 1) * 16));
        atomicAdd(&hist[b.y >> 1], 1u << ((b.y & 1) * 16));
        atomicAdd(&hist[b.z >> 1], 1u << ((b.z & 1) * 16));
        atomicAdd(&hist[b.w >> 1], 1u << ((b.w & 1) * 16));
    }
    if (blockIdx.x == 0) {  // tail (E % 8)
        for (int e = (e8 << 3) + (int)threadIdx.x; e < E; e += blockDim.x) {
            int d = dst[e];
            atomicAdd(&hist[d >> 1], 1u << ((d & 1) * 16));
        }
    }
    __syncthreads();

    for (int i = threadIdx.x; i < HWORDS; i += blockDim.x)
        g_dpart[blockIdx.x * HWORDS + i] = hist[i];  // coalesced STG
}

// ---- node1: BW-optimal deg-partial sum (1 thread/word, 4 accumulators) ----

__global__ void k_node1(const float* __restrict__ x) {
    int i = blockIdx.x * blockDim.x + threadIdx.x;
    if (i >= HWORDS) return;
    unsigned a0 = 0, a1 = 0, a2 = 0, a3 = 0;
    #pragma unroll
    for (int b = 0; b < DB; b += 4) {  // DB=148 divisible by 4
        a0 += __ldcs(&g_dpart[(b + 0) * HWORDS + i]);
        a1 += __ldcs(&g_dpart[(b + 1) * HWORDS + i]);
        a2 += __ldcs(&g_dpart[(b + 2) * HWORDS + i]);
        a3 += __ldcs(&g_dpart[(b + 3) * HWORDS + i]);
    }
    unsigned sum = (a0 + a1) + (a2 + a3);  // u16x2 lanes never overflow
    int n0 = 2 * i, n1 = 2 * i + 1;
    float d0 = rsqrtf(1.0f + (float)(sum & 0xFFFFu));   // +1 = self-loop
    float d1 = rsqrtf(1.0f + (float)(sum >> 16));
    g_dinv[n0] = d0;
    g_dinv[n1] = d1;
    g_ph[n0] = __float2half(d0 * x[n0]);
    g_ph[n1] = __float2half(d1 * x[n1]);
}

// ---- generic agg pass: 2 dst-ranges x 74 slices, smem tile, half gathers ----

__device__ __forceinline__ void agg_pass(const int* __restrict__ src,
                                         const int* __restrict__ dst, int E,
                                         const __half* __restrict__ vals,
                                         float* __restrict__ part,
                                         float* tile) {
    int range = blockIdx.x / SL;
    int slice = blockIdx.x % SL;
    int lo = range * RHALF;
    for (int i = threadIdx.x; i < RHALF; i += blockDim.x) tile[i] = 0.0f;
    __syncthreads();

    int e8 = E >> 3;
    for (int i = slice * (int)blockDim.x + (int)threadIdx.x; i < e8;
         i += SL * (int)blockDim.x) {
        int4 sa = __ldcg(reinterpret_cast<const int4*>(src) + 2 * i);
        int4 sb = __ldcg(reinterpret_cast<const int4*>(src) + 2 * i + 1);
        int4 da = __ldcg(reinterpret_cast<const int4*>(dst) + 2 * i);
        int4 db = __ldcg(reinterpret_cast<const int4*>(dst) + 2 * i + 1);
        int t0 = da.x - lo, t1 = da.y - lo, t2 = da.z - lo, t3 = da.w - lo;
        int t4 = db.x - lo, t5 = db.y - lo, t6 = db.z - lo, t7 = db.w - lo;
        // predicated gathers (no branch around the LDG)
        float v0 = ((unsigned)t0 < RHALF) ? __half2float(__ldg(&vals[sa.x])) : 0.0f;
        float v1 = ((unsigned)t1 < RHALF) ? __half2float(__ldg(&vals[sa.y])) : 0.0f;
        float v2 = ((unsigned)t2 < RHALF) ? __half2float(__ldg(&vals[sa.z])) : 0.0f;
        float v3 = ((unsigned)t3 < RHALF) ? __half2float(__ldg(&vals[sa.w])) : 0.0f;
        float v4 = ((unsigned)t4 < RHALF) ? __half2float(__ldg(&vals[sb.x])) : 0.0f;
        float v5 = ((unsigned)t5 < RHALF) ? __half2float(__ldg(&vals[sb.y])) : 0.0f;
        float v6 = ((unsigned)t6 < RHALF) ? __half2float(__ldg(&vals[sb.z])) : 0.0f;
        float v7 = ((unsigned)t7 < RHALF) ? __half2float(__ldg(&vals[sb.w])) : 0.0f;
        if ((unsigned)t0 < RHALF) atomicAdd(&tile[t0], v0);
        if ((unsigned)t1 < RHALF) atomicAdd(&tile[t1], v1);
        if ((unsigned)t2 < RHALF) atomicAdd(&tile[t2], v2);
        if ((unsigned)t3 < RHALF) atomicAdd(&tile[t3], v3);
        if ((unsigned)t4 < RHALF) atomicAdd(&tile[t4], v4);
        if ((unsigned)t5 < RHALF) atomicAdd(&tile[t5], v5);
        if ((unsigned)t6 < RHALF) atomicAdd(&tile[t6], v6);
        if ((unsigned)t7 < RHALF) atomicAdd(&tile[t7], v7);
    }
    if (slice == 0) {  // tail (E % 8), predicated by range
        for (int e = (e8 << 3) + (int)threadIdx.x; e < E; e += blockDim.x) {
            int t = dst[e] - lo;
            if ((unsigned)t < RHALF)
                atomicAdd(&tile[t], __half2float(__ldg(&vals[src[e]])));
        }
    }
    __syncthreads();

    for (int i = threadIdx.x; i < RHALF; i += blockDim.x)
        part[slice * NMAX + lo + i] = tile[i];  // coalesced STG (lo+i < NMAX always)
}

__global__ void __launch_bounds__(1024, 1)
k_agg1(const int* __restrict__ src, const int* __restrict__ dst, int E) {
    extern __shared__ float tile[];
    agg_pass(src, dst, E, g_ph, g_part1, tile);
}

__global__ void __launch_bounds__(1024, 1)
k_agg2(const int* __restrict__ src, const int* __restrict__ dst, int E) {
    extern __shared__ float tile[];
    agg_pass(src, dst, E, g_rh, g_part2, tile);
}

// ---- node2: BW-optimal agg1-partial sum + MLP; emit rho ----

__global__ void k_node2(const float* __restrict__ x,
                        const float* __restrict__ W1, const float* __restrict__ b1,
                        const float* __restrict__ W2, int n) {
    int i = blockIdx.x * blockDim.x + threadIdx.x;
    if (i >= n) return;
    float a0 = 0.f, a1 = 0.f, a2 = 0.f, a3 = 0.f;
    #pragma unroll
    for (int s = 0; s < 72; s += 4) {
        a0 += __ldcs(&g_part1[(s + 0) * NMAX + i]);
        a1 += __ldcs(&g_part1[(s + 1) * NMAX + i]);
        a2 += __ldcs(&g_part1[(s + 2) * NMAX + i]);
        a3 += __ldcs(&g_part1[(s + 3) * NMAX + i]);
    }
    a0 += __ldcs(&g_part1[72 * NMAX + i]);
    a1 += __ldcs(&g_part1[73 * NMAX + i]);
    float acc = (a0 + a1) + (a2 + a3);

    float dv = g_dinv[i];
    acc += dv * x[i];          // self-loop term (full precision)
    float sv = dv * acc;       // layer-1 aggregated scalar
    float g0 = 0.0f, g1 = 0.0f;
    #pragma unroll
    for (int j = 0; j < 16; j++) {
        float h = fmaxf(fmaf(sv, __ldg(&W1[j]), __ldg(&b1[j])), 0.0f);
        g0 = fmaf(h, __ldg(&W2[2 * j + 0]), g0);
        g1 = fmaf(h, __ldg(&W2[2 * j + 1]), g1);
    }
    float rho = dv * (g0 - g1);   // scalar layer-2 message (z0-z1 channel)
    g_rh[i] = __float2half(rho);
    g_rhof[i] = rho;
}

// ---- output: BW-optimal agg2-partial sum; 2-class log_softmax via delta ----

__global__ void k_out(const float* __restrict__ b2, float* __restrict__ out, int n) {
    int i = blockIdx.x * blockDim.x + threadIdx.x;
    if (i >= n) return;
    float db2 = __ldg(&b2[0]) - __ldg(&b2[1]);
    float a0 = 0.f, a1 = 0.f, a2 = 0.f, a3 = 0.f;
    #pragma unroll
    for (int s = 0; s < 72; s += 4) {
        a0 += __ldcs(&g_part2[(s + 0) * NMAX + i]);
        a1 += __ldcs(&g_part2[(s + 1) * NMAX + i]);
        a2 += __ldcs(&g_part2[(s + 2) * NMAX + i]);
        a3 += __ldcs(&g_part2[(s + 3) * NMAX + i]);
    }
    a0 += __ldcs(&g_part2[72 * NMAX + i]);
    a1 += __ldcs(&g_part2[73 * NMAX + i]);
    float acc = (a0 + a1) + (a2 + a3) + g_rhof[i];  // + self-loop rho

    float delta = fmaf(g_dinv[i], acc, db2);  // z0 - z1
    float l = log1pf(expf(-fabsf(delta)));
    float o0 = (delta >= 0.0f) ? -l : (delta - l);  // z0 - lse
    float o1 = o0 - delta;                          // z1 - lse
    reinterpret_cast<float2*>(out)[i] = make_float2(o0, o1);
}

// ---------------- launch ----------------

extern "C" void kernel_launch(void* const* d_in, const int* in_sizes, int n_in,
                              void* d_out, int out_size) {
    const float* x  = (const float*)d_in[0];
    const int*   ei = (const int*)  d_in[1];
    const float* W1 = (const float*)d_in[2];
    const float* b1 = (const float*)d_in[3];
    const float* W2 = (const float*)d_in[4];
    const float* b2 = (const float*)d_in[5];
    int n = in_sizes[0];        // 100000
    int E = in_sizes[1] / 2;
    const int* src = ei;
    const int* dst = ei + E;

    const int HIST_BYTES = HWORDS * 4;  // 200 KB
    const int TILE_BYTES = RHALF * 4;   // 200 KB
    cudaFuncSetAttribute(k_deg,  cudaFuncAttributeMaxDynamicSharedMemorySize, HIST_BYTES);
    cudaFuncSetAttribute(k_agg1, cudaFuncAttributeMaxDynamicSharedMemorySize, TILE_BYTES);
    cudaFuncSetAttribute(k_agg2, cudaFuncAttributeMaxDynamicSharedMemorySize, TILE_BYTES);

    const int TB = 256;
    int nb_h = (HWORDS + TB - 1) / TB;  // 196
    int nb_n = (n + TB - 1) / TB;       // 391

    k_deg  <<<DB, 1024, HIST_BYTES>>>(dst, E);
    k_node1<<<nb_h, TB>>>(x);
    k_agg1 <<<2 * SL, 1024, TILE_BYTES>>>(src, dst, E);
    k_node2<<<nb_n, TB>>>(x, W1, b1, W2, n);
    k_agg2 <<<2 * SL, 1024, TILE_BYTES>>>(src, dst, E);
    k_out  <<<nb_n, TB>>>(b2, (float*)d_out, n);
}

// round 16
// speedup vs baseline: 1.3291x; 1.0172x over previous
#include <cuda_runtime.h>
#include <cuda_fp16.h>
#include <cstdint>

#define NMAX   100000
#define HWORDS 50000          // packed uint16x2 degree words
#define RHALF  50000          // nodes per dst-range (2 ranges)
#define SL     74             // slices per range: 2*74 = 148 agg blocks
#define DB     148            // deg blocks

// Scratch (device globals; no allocation allowed)
__device__ float    g_dinv[NMAX];
__device__ __align__(16) __half   g_ph[NMAX];        // p = dinv*x (200KB)
__device__ __align__(16) __half   g_rh[NMAX];        // rho = dinv*(g0-g1) (200KB)
__device__ float    g_rhof[NMAX];                    // rho fp32 for self-loop
__device__ __align__(16) uint32_t g_dpart[DB * HWORDS];  // deg per-block partials
__device__ __align__(16) float    g_part1[SL * NMAX];    // agg1 slice partials
__device__ __align__(16) float    g_part2[SL * NMAX];    // agg2 slice partials

// -------- degree: smem hist, STG-partial flush (no REDG) --------

__global__ void k_deg(const int* __restrict__ dst, int E) {
    extern __shared__ uint32_t hist[];  // HWORDS words = 200KB
    for (int i = threadIdx.x; i < HWORDS; i += blockDim.x) hist[i] = 0u;
    __syncthreads();

    int e8 = E >> 3;
    int stride = gridDim.x * blockDim.x;
    for (int i = blockIdx.x * blockDim.x + threadIdx.x; i < e8; i += stride) {
        int4 a = __ldcg(reinterpret_cast<const int4*>(dst) + 2 * i);
        int4 b = __ldcg(reinterpret_cast<const int4*>(dst) + 2 * i + 1);
        atomicAdd(&hist[a.x >> 1], 1u << ((a.x & 1) * 16));
        atomicAdd(&hist[a.y >> 1], 1u << ((a.y & 1) * 16));
        atomicAdd(&hist[a.z >> 1], 1u << ((a.z & 1) * 16));
        atomicAdd(&hist[a.w >> 1], 1u << ((a.w & 1) * 16));
        atomicAdd(&hist[b.x >> 1], 1u << ((b.x & 1) * 16));
        atomicAdd(&hist[b.y >> 1], 1u << ((b.y & 1) * 16));
        atomicAdd(&hist[b.z >> 1], 1u << ((b.z & 1) * 16));
        atomicAdd(&hist[b.w >> 1], 1u << ((b.w & 1) * 16));
    }
    if (blockIdx.x == 0) {  // tail (E % 8)
        for (int e = (e8 << 3) + (int)threadIdx.x; e < E; e += blockDim.x) {
            int d = dst[e];
            atomicAdd(&hist[d >> 1], 1u << ((d & 1) * 16));
        }
    }
    __syncthreads();

    for (int i = threadIdx.x; i < HWORDS; i += blockDim.x)
        g_dpart[blockIdx.x * HWORDS + i] = hist[i];  // coalesced STG
}

// ---- node1: BW-optimal deg-partial sum (1 thread/word, 4 accumulators) ----

__global__ void k_node1(const float* __restrict__ x) {
    int i = blockIdx.x * blockDim.x + threadIdx.x;
    if (i >= HWORDS) return;
    unsigned a0 = 0, a1 = 0, a2 = 0, a3 = 0;
    #pragma unroll
    for (int b = 0; b < DB; b += 4) {  // DB=148 divisible by 4
        a0 += __ldcs(&g_dpart[(b + 0) * HWORDS + i]);
        a1 += __ldcs(&g_dpart[(b + 1) * HWORDS + i]);
        a2 += __ldcs(&g_dpart[(b + 2) * HWORDS + i]);
        a3 += __ldcs(&g_dpart[(b + 3) * HWORDS + i]);
    }
    unsigned sum = (a0 + a1) + (a2 + a3);  // u16x2 lanes never overflow
    int n0 = 2 * i, n1 = 2 * i + 1;
    float d0 = rsqrtf(1.0f + (float)(sum & 0xFFFFu));   // +1 = self-loop
    float d1 = rsqrtf(1.0f + (float)(sum >> 16));
    g_dinv[n0] = d0;
    g_dinv[n1] = d1;
    g_ph[n0] = __float2half(d0 * x[n0]);
    g_ph[n1] = __float2half(d1 * x[n1]);
}

// ---- agg pass: 2 dst-ranges x 74 slices, TRULY predicated gather+scatter ----

__device__ __forceinline__ void agg_pass(const int* __restrict__ src,
                                         const int* __restrict__ dst, int E,
                                         const __half* __restrict__ vals,
                                         float* __restrict__ part,
                                         float* tile) {
    int range = blockIdx.x / SL;
    int slice = blockIdx.x % SL;
    int lo = range * RHALF;
    for (int i = threadIdx.x; i < RHALF; i += blockDim.x) tile[i] = 0.0f;
    __syncthreads();

    int e8 = E >> 3;
    for (int i = slice * (int)blockDim.x + (int)threadIdx.x; i < e8;
         i += SL * (int)blockDim.x) {
        int4 sa = __ldcg(reinterpret_cast<const int4*>(src) + 2 * i);
        int4 sb = __ldcg(reinterpret_cast<const int4*>(src) + 2 * i + 1);
        int4 da = __ldcg(reinterpret_cast<const int4*>(dst) + 2 * i);
        int4 db = __ldcg(reinterpret_cast<const int4*>(dst) + 2 * i + 1);
        int t0 = da.x - lo, t1 = da.y - lo, t2 = da.z - lo, t3 = da.w - lo;
        int t4 = db.x - lo, t5 = db.y - lo, t6 = db.z - lo, t7 = db.w - lo;
        // guarded gather + scatter: @P LDG / @P ATOMS, off-lanes issue no wavefront
        if ((unsigned)t0 < RHALF) atomicAdd(&tile[t0], __half2float(__ldg(&vals[sa.x])));
        if ((unsigned)t1 < RHALF) atomicAdd(&tile[t1], __half2float(__ldg(&vals[sa.y])));
        if ((unsigned)t2 < RHALF) atomicAdd(&tile[t2], __half2float(__ldg(&vals[sa.z])));
        if ((unsigned)t3 < RHALF) atomicAdd(&tile[t3], __half2float(__ldg(&vals[sa.w])));
        if ((unsigned)t4 < RHALF) atomicAdd(&tile[t4], __half2float(__ldg(&vals[sb.x])));
        if ((unsigned)t5 < RHALF) atomicAdd(&tile[t5], __half2float(__ldg(&vals[sb.y])));
        if ((unsigned)t6 < RHALF) atomicAdd(&tile[t6], __half2float(__ldg(&vals[sb.z])));
        if ((unsigned)t7 < RHALF) atomicAdd(&tile[t7], __half2float(__ldg(&vals[sb.w])));
    }
    if (slice == 0) {  // tail (E % 8), predicated by range
        for (int e = (e8 << 3) + (int)threadIdx.x; e < E; e += blockDim.x) {
            int t = dst[e] - lo;
            if ((unsigned)t < RHALF)
                atomicAdd(&tile[t], __half2float(__ldg(&vals[src[e]])));
        }
    }
    __syncthreads();

    for (int i = threadIdx.x; i < RHALF; i += blockDim.x)
        part[slice * NMAX + lo + i] = tile[i];  // coalesced STG
}

__global__ void __launch_bounds__(1024, 1)
k_agg1(const int* __restrict__ src, const int* __restrict__ dst, int E) {
    extern __shared__ float tile[];
    agg_pass(src, dst, E, g_ph, g_part1, tile);
}

__global__ void __launch_bounds__(1024, 1)
k_agg2(const int* __restrict__ src, const int* __restrict__ dst, int E) {
    extern __shared__ float tile[];
    agg_pass(src, dst, E, g_rh, g_part2, tile);
}

// ---- node2: BW-optimal agg1-partial sum + MLP; emit rho ----

__global__ void k_node2(const float* __restrict__ x,
                        const float* __restrict__ W1, const float* __restrict__ b1,
                        const float* __restrict__ W2, int n) {
    int i = blockIdx.x * blockDim.x + threadIdx.x;
    if (i >= n) return;
    float a0 = 0.f, a1 = 0.f, a2 = 0.f, a3 = 0.f;
    #pragma unroll
    for (int s = 0; s < 72; s += 4) {
        a0 += __ldcs(&g_part1[(s + 0) * NMAX + i]);
        a1 += __ldcs(&g_part1[(s + 1) * NMAX + i]);
        a2 += __ldcs(&g_part1[(s + 2) * NMAX + i]);
        a3 += __ldcs(&g_part1[(s + 3) * NMAX + i]);
    }
    a0 += __ldcs(&g_part1[72 * NMAX + i]);
    a1 += __ldcs(&g_part1[73 * NMAX + i]);
    float acc = (a0 + a1) + (a2 + a3);

    float dv = g_dinv[i];
    acc += dv * x[i];          // self-loop term (full precision)
    float sv = dv * acc;       // layer-1 aggregated scalar
    float g0 = 0.0f, g1 = 0.0f;
    #pragma unroll
    for (int j = 0; j < 16; j++) {
        float h = fmaxf(fmaf(sv, __ldg(&W1[j]), __ldg(&b1[j])), 0.0f);
        g0 = fmaf(h, __ldg(&W2[2 * j + 0]), g0);
        g1 = fmaf(h, __ldg(&W2[2 * j + 1]), g1);
    }
    float rho = dv * (g0 - g1);   // scalar layer-2 message (z0-z1 channel)
    g_rh[i] = __float2half(rho);
    g_rhof[i] = rho;
}

// ---- output: BW-optimal agg2-partial sum; 2-class log_softmax via delta ----

__global__ void k_out(const float* __restrict__ b2, float* __restrict__ out, int n) {
    int i = blockIdx.x * blockDim.x + threadIdx.x;
    if (i >= n) return;
    float db2 = __ldg(&b2[0]) - __ldg(&b2[1]);
    float a0 = 0.f, a1 = 0.f, a2 = 0.f, a3 = 0.f;
    #pragma unroll
    for (int s = 0; s < 72; s += 4) {
        a0 += __ldcs(&g_part2[(s + 0) * NMAX + i]);
        a1 += __ldcs(&g_part2[(s + 1) * NMAX + i]);
        a2 += __ldcs(&g_part2[(s + 2) * NMAX + i]);
        a3 += __ldcs(&g_part2[(s + 3) * NMAX + i]);
    }
    a0 += __ldcs(&g_part2[72 * NMAX + i]);
    a1 += __ldcs(&g_part2[73 * NMAX + i]);
    float acc = (a0 + a1) + (a2 + a3) + g_rhof[i];  // + self-loop rho

    float delta = fmaf(g_dinv[i], acc, db2);  // z0 - z1
    float l = log1pf(expf(-fabsf(delta)));
    float o0 = (delta >= 0.0f) ? -l : (delta - l);  // z0 - lse
    float o1 = o0 - delta;                          // z1 - lse
    reinterpret_cast<float2*>(out)[i] = make_float2(o0, o1);
}

// ---------------- launch ----------------

extern "C" void kernel_launch(void* const* d_in, const int* in_sizes, int n_in,
                              void* d_out, int out_size) {
    const float* x  = (const float*)d_in[0];
    const int*   ei = (const int*)  d_in[1];
    const float* W1 = (const float*)d_in[2];
    const float* b1 = (const float*)d_in[3];
    const float* W2 = (const float*)d_in[4];
    const float* b2 = (const float*)d_in[5];
    int n = in_sizes[0];        // 100000
    int E = in_sizes[1] / 2;
    const int* src = ei;
    const int* dst = ei + E;

    const int HIST_BYTES = HWORDS * 4;  // 200 KB
    const int TILE_BYTES = RHALF * 4;   // 200 KB
    cudaFuncSetAttribute(k_deg,  cudaFuncAttributeMaxDynamicSharedMemorySize, HIST_BYTES);
    cudaFuncSetAttribute(k_agg1, cudaFuncAttributeMaxDynamicSharedMemorySize, TILE_BYTES);
    cudaFuncSetAttribute(k_agg2, cudaFuncAttributeMaxDynamicSharedMemorySize, TILE_BYTES);

    const int TB = 256;
    int nb_h = (HWORDS + TB - 1) / TB;  // 196
    int nb_n = (n + TB - 1) / TB;       // 391

    k_deg  <<<DB, 1024, HIST_BYTES>>>(dst, E);
    k_node1<<<nb_h, TB>>>(x);
    k_agg1 <<<2 * SL, 1024, TILE_BYTES>>>(src, dst, E);
    k_node2<<<nb_n, TB>>>(x, W1, b1, W2, n);
    k_agg2 <<<2 * SL, 1024, TILE_BYTES>>>(src, dst, E);
    k_out  <<<nb_n, TB>>>(b2, (float*)d_out, n);
}